// round 1
// baseline (speedup 1.0000x reference)
#include <cuda_runtime.h>
#include <math.h>

#define NN   40000
#define EE   640000
#define FIN  33
#define HH   128
#define LL   8
#define ALPHA 0.1f

// ---------------- scratch (no allocation allowed) ----------------
__device__ float g_x0[NN * HH];
__device__ float g_xc[NN * HH];
__device__ float g_xx[NN * HH];
__device__ int   g_rowptr[NN + 1];
__device__ int   g_off[NN];
__device__ int   g_cnt[NN];
__device__ int   g_cols[EE];
__device__ float g_w[EE];

// ---------------- input projection: x0 = relu(x @ W_in^T + b_in) ----------------
// 128 threads per block, 32 rows per block.
__global__ void input_proj_kernel(const float* __restrict__ x,
                                  const float* __restrict__ Win,
                                  const float* __restrict__ bin) {
    __shared__ float sW[HH * FIN];
    __shared__ float sx[FIN];
    int tid = threadIdx.x;
    for (int i = tid; i < HH * FIN; i += 128) sW[i] = Win[i];
    float b = bin[tid];
    int row0 = blockIdx.x * 32;
    for (int r = 0; r < 32; r++) {
        int row = row0 + r;
        __syncthreads();
        if (tid < FIN) sx[tid] = x[row * FIN + tid];
        __syncthreads();
        float s = b;
#pragma unroll
        for (int f = 0; f < FIN; f++) s += sW[tid * FIN + f] * sx[f];
        s = fmaxf(s, 0.0f);
        g_x0[row * HH + tid] = s;
        g_xc[row * HH + tid] = s;
    }
}

// ---------------- CSR build ----------------
__global__ void zero_cnt_kernel() {
    int i = blockIdx.x * blockDim.x + threadIdx.x;
    if (i < NN) g_cnt[i] = 0;
}

__global__ void count_kernel(const int* __restrict__ er) {
    int e = blockIdx.x * blockDim.x + threadIdx.x;
    if (e < EE) atomicAdd(&g_cnt[er[e]], 1);
}

// single-block exclusive scan over NN counts
__global__ void scan_kernel() {
    __shared__ int sdata[1024];
    int tid = threadIdx.x;
    int carry = 0;
    for (int base = 0; base < NN; base += 1024) {
        int i = base + tid;
        int v = (i < NN) ? g_cnt[i] : 0;
        sdata[tid] = v;
        __syncthreads();
        for (int off = 1; off < 1024; off <<= 1) {
            int t = (tid >= off) ? sdata[tid - off] : 0;
            __syncthreads();
            sdata[tid] += t;
            __syncthreads();
        }
        if (i < NN) {
            int excl = carry + sdata[tid] - v;
            g_rowptr[i] = excl;
            g_off[i] = excl;
        }
        carry += sdata[1023];
        __syncthreads();
    }
    if (tid == 0) g_rowptr[NN] = carry;
}

__global__ void scatter_kernel(const int* __restrict__ er,
                               const int* __restrict__ ec,
                               const float* __restrict__ ew) {
    int e = blockIdx.x * blockDim.x + threadIdx.x;
    if (e < EE) {
        int r = er[e];
        int p = atomicAdd(&g_off[r], 1);
        g_cols[p] = ec[e];
        g_w[p] = ew[e];
    }
}

// ---------------- SpMM + alpha combine: xx = 0.9 * (A @ xc) + 0.1 * x0 ----------------
// one warp per row; lane owns 4 contiguous features (float4)
__global__ void spmm_kernel() {
    int gt = blockIdx.x * blockDim.x + threadIdx.x;
    int row = gt >> 5;
    int lane = threadIdx.x & 31;
    if (row >= NN) return;
    int s = g_rowptr[row];
    int e = g_rowptr[row + 1];
    float4 acc = make_float4(0.f, 0.f, 0.f, 0.f);
    const float4* xc4 = (const float4*)g_xc;
    for (int i = s; i < e; i++) {
        int c = g_cols[i];
        float w = g_w[i];
        float4 v = xc4[c * 32 + lane];
        acc.x += w * v.x; acc.y += w * v.y; acc.z += w * v.z; acc.w += w * v.w;
    }
    float4 x0v = ((const float4*)g_x0)[row * 32 + lane];
    float4 o;
    o.x = (1.0f - ALPHA) * acc.x + ALPHA * x0v.x;
    o.y = (1.0f - ALPHA) * acc.y + ALPHA * x0v.y;
    o.z = (1.0f - ALPHA) * acc.z + ALPHA * x0v.z;
    o.w = (1.0f - ALPHA) * acc.w + ALPHA * x0v.w;
    ((float4*)g_xx)[row * 32 + lane] = o;
}

// ---------------- layer GEMM + GCNII epilogue ----------------
// acc = xx @ W ; out = (1-beta)*xx + beta*acc ; xc += relu(out)
// BM=64, BN=128, BK=16, 256 threads, thread tile 8x4
__global__ void layer_gemm_kernel(const float* __restrict__ W, float beta) {
    __shared__ float As[16][68];   // [k][m], padded stride 68 (16B-aligned rows)
    __shared__ float Bs[16][128];  // [k][n]
    int tid = threadIdx.x;
    int tx = tid & 31;   // 32 col-groups of 4
    int ty = tid >> 5;   // 8 row-groups of 8
    int r0 = blockIdx.x * 64;

    float acc[8][4];
#pragma unroll
    for (int i = 0; i < 8; i++)
#pragma unroll
        for (int j = 0; j < 4; j++) acc[i][j] = 0.f;

    for (int k0 = 0; k0 < HH; k0 += 16) {
        {   // load As: 64 rows x 16 k, each thread one float4 along k
            int m = tid >> 2, kq = tid & 3;
            float4 v = *(const float4*)&g_xx[(r0 + m) * HH + k0 + kq * 4];
            As[kq * 4 + 0][m] = v.x;
            As[kq * 4 + 1][m] = v.y;
            As[kq * 4 + 2][m] = v.z;
            As[kq * 4 + 3][m] = v.w;
        }
        {   // load Bs: 16 k x 128 n, each thread two float4
#pragma unroll
            for (int i = 0; i < 2; i++) {
                int idx = tid * 2 + i;
                int k = idx >> 5, c4 = idx & 31;
                *(float4*)&Bs[k][c4 * 4] = *(const float4*)&W[(k0 + k) * HH + c4 * 4];
            }
        }
        __syncthreads();
#pragma unroll
        for (int k = 0; k < 16; k++) {
            float4 a0 = *(const float4*)&As[k][ty * 8];
            float4 a1 = *(const float4*)&As[k][ty * 8 + 4];
            float4 bb = *(const float4*)&Bs[k][tx * 4];
            float av[8] = {a0.x, a0.y, a0.z, a0.w, a1.x, a1.y, a1.z, a1.w};
            float bv[4] = {bb.x, bb.y, bb.z, bb.w};
#pragma unroll
            for (int rr = 0; rr < 8; rr++)
#pragma unroll
                for (int cc = 0; cc < 4; cc++)
                    acc[rr][cc] += av[rr] * bv[cc];
        }
        __syncthreads();
    }

    float omb = 1.0f - beta;
#pragma unroll
    for (int rr = 0; rr < 8; rr++) {
        int row = r0 + ty * 8 + rr;
        float4 xxv = *(const float4*)&g_xx[row * HH + tx * 4];
        float4 xcv = *(float4*)&g_xc[row * HH + tx * 4];
        float4 o;
        o.x = omb * xxv.x + beta * acc[rr][0];
        o.y = omb * xxv.y + beta * acc[rr][1];
        o.z = omb * xxv.z + beta * acc[rr][2];
        o.w = omb * xxv.w + beta * acc[rr][3];
        xcv.x += fmaxf(o.x, 0.f);
        xcv.y += fmaxf(o.y, 0.f);
        xcv.z += fmaxf(o.z, 0.f);
        xcv.w += fmaxf(o.w, 0.f);
        *(float4*)&g_xc[row * HH + tx * 4] = xcv;
    }
}

// ---------------- output projection: out = xc @ W_out^T + b_out ----------------
__global__ void out_proj_kernel(const float* __restrict__ Wout,
                                const float* __restrict__ bout,
                                float* __restrict__ out) {
    int gt = blockIdx.x * blockDim.x + threadIdx.x;
    int row = gt >> 5;
    int lane = threadIdx.x & 31;
    if (row >= NN) return;
    float4 v = ((const float4*)g_xc)[row * 32 + lane];
#pragma unroll
    for (int c = 0; c < 3; c++) {
        float4 w = *(const float4*)&Wout[c * HH + lane * 4];
        float s = v.x * w.x + v.y * w.y + v.z * w.z + v.w * w.w;
#pragma unroll
        for (int o = 16; o; o >>= 1) s += __shfl_down_sync(0xFFFFFFFFu, s, o);
        if (lane == 0) out[row * 3 + c] = s + bout[c];
    }
}

extern "C" void kernel_launch(void* const* d_in, const int* in_sizes, int n_in,
                              void* d_out, int out_size) {
    const float* x    = (const float*)d_in[0];
    const int*   er   = (const int*)d_in[1];
    const int*   ec   = (const int*)d_in[2];
    const float* ew   = (const float*)d_in[3];
    const float* Win  = (const float*)d_in[4];
    const float* bin  = (const float*)d_in[5];
    const float* Wout = (const float*)d_in[6];
    const float* bout = (const float*)d_in[7];
    const float* Wc   = (const float*)d_in[8];
    float* out = (float*)d_out;

    input_proj_kernel<<<NN / 32, 128>>>(x, Win, bin);
    zero_cnt_kernel<<<(NN + 255) / 256, 256>>>();
    count_kernel<<<(EE + 255) / 256, 256>>>(er);
    scan_kernel<<<1, 1024>>>();
    scatter_kernel<<<(EE + 255) / 256, 256>>>(er, ec, ew);

    for (int l = 0; l < LL; l++) {
        float beta = logf(0.5f / (float)(l + 1) + 1.0f);
        spmm_kernel<<<(NN * 32 + 255) / 256, 256>>>();
        layer_gemm_kernel<<<NN / 64, 256>>>(Wc + (size_t)l * HH * HH, beta);
    }

    out_proj_kernel<<<(NN * 32 + 255) / 256, 256>>>(Wout, bout, out);
}